// round 12
// baseline (speedup 1.0000x reference)
#include <cuda_runtime.h>
#include <cuda_fp16.h>

#define B      64
#define TAPE   262144
#define OUT    65536
#define FANIN  16

// Scratch (allocation-free rule: __device__ globals)
__device__ __half g_tape_T[(size_t)TAPE * B];  // 32 MB: tape^T in fp16 [TAPE, B]
__device__ int    g_is64;                      // 1 if index arrays are int64

// ---------------------------------------------------------------------------
// K1: single pass over tape [B, TAPE], 128 cols per block, 256 threads:
//   (a) out = tape              (8 independent float4 ldcs -> stcs, MLP=8)
//   (b) g_tape_T = (half)tape^T (16B stores, default policy -> L2-resident)
//   (c) block 0 publishes index dtype (int64 high words all zero)
// Measured ~18us for 128MB mandatory DRAM (~7.1TB/s) — at floor, frozen.
// ---------------------------------------------------------------------------
__global__ void __launch_bounds__(256)
transpose_copy_probe_kernel(const float* __restrict__ tape,
                            float* __restrict__ out,
                            const int* __restrict__ in_idx_w) {
    __shared__ float s[2][64][65];   // [tile][col][batch]
    const int t  = threadIdx.x;      // 0..255
    const int bk = blockIdx.x;       // 0..2047
    const int t0 = bk * 128;         // tape-col base (2 tiles of 64)

    // Phase A: 8 independent float4 loads, then stores + smem staging
    const int q = t & 15;            // col quad within tile
    const int b = t >> 4;            // 0..15 (batch base)
    float4 v[8];
    size_t off[8];
    #pragma unroll
    for (int u = 0; u < 8; u++) {
        const int tile  = u & 1;
        const int batch = b + 16 * (u >> 1);     // 0..63
        off[u] = (size_t)batch * TAPE + t0 + tile * 64 + 4 * q;
        v[u] = __ldcs((const float4*)(tape + off[u]));
    }
    #pragma unroll
    for (int u = 0; u < 8; u++) {
        __stcs((float4*)(out + off[u]), v[u]);
        const int tile  = u & 1;
        const int batch = b + 16 * (u >> 1);
        s[tile][4 * q + 0][batch] = v[u].x;
        s[tile][4 * q + 1][batch] = v[u].y;
        s[tile][4 * q + 2][batch] = v[u].z;
        s[tile][4 * q + 3][batch] = v[u].w;
    }

    // Dtype probe (block 0): int64 => high words of small indices all zero
    if (bk == 0 && t < 32) {
        const bool ok = (in_idx_w[2 * t + 1] == 0) &&
                        (in_idx_w[2 * (t + 32) + 1] == 0);
        const unsigned m = __ballot_sync(0xffffffffu, ok);
        if (t == 0) g_is64 = (m == 0xffffffffu) ? 1 : 0;
    }
    __syncthreads();

    // Phase B: fp16 convert + write tape_T (4 x 16B stores per thread)
    #pragma unroll
    for (int u2 = 0; u2 < 4; u2++) {
        const int idx  = t + 256 * u2;   // 0..1023
        const int row  = idx >> 3;       // 0..127 (col within block)
        const int g    = idx & 7;        // batch octet
        const int tile = row >> 6;
        const int c    = row & 63;
        __half2 h[4];
        #pragma unroll
        for (int k = 0; k < 4; k++)
            h[k] = __floats2half2_rn(s[tile][c][8 * g + 2 * k],
                                     s[tile][c][8 * g + 2 * k + 1]);
        *(uint4*)(g_tape_T + (size_t)(t0 + row) * B + 8 * g) = *(uint4*)h;
    }
}

// ---------------------------------------------------------------------------
// K2: fused gather + weighted-sum + activation + scatter.
// Block = 16 warps x 2 outputs = 32 outputs. SPLIT-WARP gather: lanes 0-15
// serve output A, lanes 16-31 output B; each lane loads a uint2 (= 2 half2
// = 4 batches) of its output's 128B tape_T row. Same L2 sectors as before,
// ~36% fewer instructions (1 LDS.64 + 1 LDG.64 + 2 cvt + 4 FFMA per f).
// Scatter goes through s_oi (real output_indices): coalesced when arange.
// ---------------------------------------------------------------------------
__global__ void __launch_bounds__(512)
gather_scatter_kernel(const float* __restrict__ weights,
                      const float* __restrict__ bias,
                      const void*  __restrict__ input_indices,
                      const void*  __restrict__ output_indices,
                      const void*  __restrict__ act_ids,
                      float* __restrict__ out) {
    __shared__ int2  s_iw[512];      // 32 outputs x 16 fanin: (byte_off, w bits)
    __shared__ float s_bias[32];
    __shared__ int   s_act[32];
    __shared__ int   s_oi[32];
    __shared__ float sx[32][66];     // [output][batch]

    const int t    = threadIdx.x;    // 0..511
    const int o0   = blockIdx.x * 32;
    const int is64 = g_is64;

    {
        const int idx = is64 ? (int)((const long long*)input_indices)[(size_t)o0 * FANIN + t]
                             : ((const int*)input_indices)[(size_t)o0 * FANIN + t];
        const float w = weights[(size_t)o0 * FANIN + t];
        s_iw[t] = make_int2(idx * (B * 2), __float_as_int(w));  // byte offset into fp16 tape_T
    }
    if (t < 32) {
        s_bias[t] = bias[o0 + t];
        s_act[t]  = is64 ? (int)((const long long*)act_ids)[o0 + t]
                         : ((const int*)act_ids)[o0 + t];
        s_oi[t]   = is64 ? (int)((const long long*)output_indices)[o0 + t]
                         : ((const int*)output_indices)[o0 + t];
    }
    __syncthreads();

    const int warp = t >> 5;             // 0..15
    const int lane = t & 31;
    const int ow   = 2 * warp + (lane >> 4);   // this half-warp's output
    const int c    = lane & 15;                // batch quad: batches 4c..4c+3
    const char* tTr = (const char*)g_tape_T + c * 8;

    const float bv = s_bias[ow];
    float4 acc = make_float4(bv, bv, bv, bv);

    #pragma unroll
    for (int f = 0; f < FANIN; f++) {
        const int2 iw = s_iw[ow * FANIN + f];       // 2-addr broadcast LDS.64
        const uint2 raw = *(const uint2*)(tTr + iw.x);
        const float2 v0 = __half22float2(*(const __half2*)&raw.x);
        const float2 v1 = __half22float2(*(const __half2*)&raw.y);
        const float w = __int_as_float(iw.y);
        acc.x = fmaf(w, v0.x, acc.x);
        acc.y = fmaf(w, v0.y, acc.y);
        acc.z = fmaf(w, v1.x, acc.z);
        acc.w = fmaf(w, v1.y, acc.w);
    }

    const int a = s_act[ow];
    if (a == 0) {
        acc.x = fmaxf(acc.x, 0.f); acc.y = fmaxf(acc.y, 0.f);
        acc.z = fmaxf(acc.z, 0.f); acc.w = fmaxf(acc.w, 0.f);
    } else if (a == 1) {
        acc.x = 1.f / (1.f + __expf(-acc.x));
        acc.y = 1.f / (1.f + __expf(-acc.y));
        acc.z = 1.f / (1.f + __expf(-acc.z));
        acc.w = 1.f / (1.f + __expf(-acc.w));
    } else {
        acc.x = tanhf(acc.x); acc.y = tanhf(acc.y);
        acc.z = tanhf(acc.z); acc.w = tanhf(acc.w);
    }

    sx[ow][4 * c + 0] = acc.x;
    sx[ow][4 * c + 1] = acc.y;
    sx[ow][4 * c + 2] = acc.z;
    sx[ow][4 * c + 3] = acc.w;
    __syncthreads();

    // Scatter: thread t -> output column s_oi[t&31], 4 batches (t>>5 + 16r).
    // 32 consecutive threads -> 128B contiguous per batch row when arange.
    const int j  = t & 31;
    const int b0 = t >> 5;           // 0..15
    const int oi = s_oi[j];
    #pragma unroll
    for (int r = 0; r < 4; r++)
        __stcs(out + (size_t)(b0 + 16 * r) * TAPE + oi, sx[j][b0 + 16 * r]);
}

// ---------------------------------------------------------------------------
extern "C" void kernel_launch(void* const* d_in, const int* in_sizes, int n_in,
                              void* d_out, int out_size) {
    const float* tape           = (const float*)d_in[0];
    const float* weights        = (const float*)d_in[1];
    const float* bias           = (const float*)d_in[2];
    const void*  input_indices  = d_in[3];
    const void*  output_indices = d_in[4];
    const void*  act_ids        = d_in[5];
    float* out = (float*)d_out;

    // K1: read tape once -> copy to out + fp16 transpose to tape_T (+ dtype)
    transpose_copy_probe_kernel<<<TAPE / 128, 256>>>(
        tape, out, (const int*)input_indices);

    // K2: gather + dot + activation + scatter through real output_indices
    gather_scatter_kernel<<<OUT / 32, 512>>>(weights, bias, input_indices,
                                             output_indices, act_ids, out);
}

// round 13
// speedup vs baseline: 1.0163x; 1.0163x over previous
#include <cuda_runtime.h>
#include <cuda_fp16.h>

#define B      64
#define TAPE   262144
#define OUT    65536
#define FANIN  16

// Scratch (allocation-free rule: __device__ globals)
__device__ __half g_tape_T[(size_t)TAPE * B];  // 32 MB: tape^T in fp16 [TAPE, B]
__device__ int    g_is64;                      // 1 if index arrays are int64

// ---------------------------------------------------------------------------
// K1: single pass over tape [B, TAPE], 128 cols per block, 256 threads:
//   (a) out = tape              (8 independent float4 ldcs -> stcs, MLP=8)
//   (b) g_tape_T = (half)tape^T (16B stores, default policy -> L2-resident)
//   (c) block 0 publishes index dtype (int64 high words all zero)
// Measured ~18us for its mandatory DRAM stream — at floor, frozen.
// ---------------------------------------------------------------------------
__global__ void __launch_bounds__(256)
transpose_copy_probe_kernel(const float* __restrict__ tape,
                            float* __restrict__ out,
                            const int* __restrict__ in_idx_w) {
    __shared__ float s[2][64][65];   // [tile][col][batch]
    const int t  = threadIdx.x;      // 0..255
    const int bk = blockIdx.x;       // 0..2047
    const int t0 = bk * 128;         // tape-col base (2 tiles of 64)

    // Phase A: 8 independent float4 loads, then stores + smem staging
    const int q = t & 15;            // col quad within tile
    const int b = t >> 4;            // 0..15 (batch base)
    float4 v[8];
    size_t off[8];
    #pragma unroll
    for (int u = 0; u < 8; u++) {
        const int tile  = u & 1;
        const int batch = b + 16 * (u >> 1);     // 0..63
        off[u] = (size_t)batch * TAPE + t0 + tile * 64 + 4 * q;
        v[u] = __ldcs((const float4*)(tape + off[u]));
    }
    #pragma unroll
    for (int u = 0; u < 8; u++) {
        __stcs((float4*)(out + off[u]), v[u]);
        const int tile  = u & 1;
        const int batch = b + 16 * (u >> 1);
        s[tile][4 * q + 0][batch] = v[u].x;
        s[tile][4 * q + 1][batch] = v[u].y;
        s[tile][4 * q + 2][batch] = v[u].z;
        s[tile][4 * q + 3][batch] = v[u].w;
    }

    // Dtype probe (block 0): int64 => high words of small indices all zero
    if (bk == 0 && t < 32) {
        const bool ok = (in_idx_w[2 * t + 1] == 0) &&
                        (in_idx_w[2 * (t + 32) + 1] == 0);
        const unsigned m = __ballot_sync(0xffffffffu, ok);
        if (t == 0) g_is64 = (m == 0xffffffffu) ? 1 : 0;
    }
    __syncthreads();

    // Phase B: fp16 convert + write tape_T (4 x 16B stores per thread)
    #pragma unroll
    for (int u2 = 0; u2 < 4; u2++) {
        const int idx  = t + 256 * u2;   // 0..1023
        const int row  = idx >> 3;       // 0..127 (col within block)
        const int g    = idx & 7;        // batch octet
        const int tile = row >> 6;
        const int c    = row & 63;
        __half2 h[4];
        #pragma unroll
        for (int k = 0; k < 4; k++)
            h[k] = __floats2half2_rn(s[tile][c][8 * g + 2 * k],
                                     s[tile][c][8 * g + 2 * k + 1]);
        *(uint4*)(g_tape_T + (size_t)(t0 + row) * B + 8 * g) = *(uint4*)h;
    }
}

// ---------------------------------------------------------------------------
// K2: fused gather + weighted-sum + activation + scatter, HFMA2 inner loop.
// Block = 16 warps x 2 outputs = 32 outputs. Split-warp gather: lanes 0-15
// serve output A, 16-31 output B; lane loads uint2 (4 batches) of the 128B
// tape_T row. Weights live in smem as pre-broadcast half2; the dot runs as
// 2 HFMA2 per (f, 4 batches) into fp16 partial accumulators (2 f-groups of 8
// per batch-pair to bound rounding), combined + bias + activation in fp32.
// Scatter goes through s_oi (real output_indices): coalesced when arange.
// ---------------------------------------------------------------------------
__global__ void __launch_bounds__(512)
gather_scatter_kernel(const float* __restrict__ weights,
                      const float* __restrict__ bias,
                      const void*  __restrict__ input_indices,
                      const void*  __restrict__ output_indices,
                      const void*  __restrict__ act_ids,
                      float* __restrict__ out) {
    __shared__ int2  s_iw[512];      // 32 outputs x 16 fanin: (byte_off, half2 w)
    __shared__ float s_bias[32];
    __shared__ int   s_act[32];
    __shared__ int   s_oi[32];
    __shared__ float sx[32][66];     // [output][batch]

    const int t    = threadIdx.x;    // 0..511
    const int o0   = blockIdx.x * 32;
    const int is64 = g_is64;

    {
        const int idx = is64 ? (int)((const long long*)input_indices)[(size_t)o0 * FANIN + t]
                             : ((const int*)input_indices)[(size_t)o0 * FANIN + t];
        const float w = weights[(size_t)o0 * FANIN + t];
        const __half2 wh = __floats2half2_rn(w, w);
        int whbits;
        *(__half2*)&whbits = wh;
        s_iw[t] = make_int2(idx * (B * 2), whbits);
    }
    if (t < 32) {
        s_bias[t] = bias[o0 + t];
        s_act[t]  = is64 ? (int)((const long long*)act_ids)[o0 + t]
                         : ((const int*)act_ids)[o0 + t];
        s_oi[t]   = is64 ? (int)((const long long*)output_indices)[o0 + t]
                         : ((const int*)output_indices)[o0 + t];
    }
    __syncthreads();

    const int warp = t >> 5;             // 0..15
    const int lane = t & 31;
    const int ow   = 2 * warp + (lane >> 4);   // this half-warp's output
    const int c    = lane & 15;                // batch quad: batches 4c..4c+3
    const char* tTr = (const char*)g_tape_T + c * 8;

    // fp16 partial accumulators: [batch-pair][f-group]
    __half2 p0a = __float2half2_rn(0.f), p0b = __float2half2_rn(0.f);
    __half2 p1a = __float2half2_rn(0.f), p1b = __float2half2_rn(0.f);

    #pragma unroll
    for (int f = 0; f < FANIN; f++) {
        const int2 iw = s_iw[ow * FANIN + f];       // broadcast LDS.64
        const uint2 raw = *(const uint2*)(tTr + iw.x);
        const __half2 wv = *(const __half2*)&iw.y;
        const __half2 v0 = *(const __half2*)&raw.x;
        const __half2 v1 = *(const __half2*)&raw.y;
        if (f < 8) {
            p0a = __hfma2(wv, v0, p0a);
            p1a = __hfma2(wv, v1, p1a);
        } else {
            p0b = __hfma2(wv, v0, p0b);
            p1b = __hfma2(wv, v1, p1b);
        }
    }

    // Combine partials + bias in fp32
    const float bv = s_bias[ow];
    const float2 f0a = __half22float2(p0a), f0b = __half22float2(p0b);
    const float2 f1a = __half22float2(p1a), f1b = __half22float2(p1b);
    float4 acc;
    acc.x = bv + f0a.x + f0b.x;
    acc.y = bv + f0a.y + f0b.y;
    acc.z = bv + f1a.x + f1b.x;
    acc.w = bv + f1a.y + f1b.y;

    const int a = s_act[ow];
    if (a == 0) {
        acc.x = fmaxf(acc.x, 0.f); acc.y = fmaxf(acc.y, 0.f);
        acc.z = fmaxf(acc.z, 0.f); acc.w = fmaxf(acc.w, 0.f);
    } else if (a == 1) {
        acc.x = 1.f / (1.f + __expf(-acc.x));
        acc.y = 1.f / (1.f + __expf(-acc.y));
        acc.z = 1.f / (1.f + __expf(-acc.z));
        acc.w = 1.f / (1.f + __expf(-acc.w));
    } else {
        acc.x = tanhf(acc.x); acc.y = tanhf(acc.y);
        acc.z = tanhf(acc.z); acc.w = tanhf(acc.w);
    }

    sx[ow][4 * c + 0] = acc.x;
    sx[ow][4 * c + 1] = acc.y;
    sx[ow][4 * c + 2] = acc.z;
    sx[ow][4 * c + 3] = acc.w;
    __syncthreads();

    // Scatter: thread t -> output column s_oi[t&31], 4 batches (t>>5 + 16r).
    // 32 consecutive threads -> 128B contiguous per batch row when arange.
    const int j  = t & 31;
    const int b0 = t >> 5;           // 0..15
    const int oi = s_oi[j];
    #pragma unroll
    for (int r = 0; r < 4; r++)
        __stcs(out + (size_t)(b0 + 16 * r) * TAPE + oi, sx[j][b0 + 16 * r]);
}

// ---------------------------------------------------------------------------
extern "C" void kernel_launch(void* const* d_in, const int* in_sizes, int n_in,
                              void* d_out, int out_size) {
    const float* tape           = (const float*)d_in[0];
    const float* weights        = (const float*)d_in[1];
    const float* bias           = (const float*)d_in[2];
    const void*  input_indices  = d_in[3];
    const void*  output_indices = d_in[4];
    const void*  act_ids        = d_in[5];
    float* out = (float*)d_out;

    // K1: read tape once -> copy to out + fp16 transpose to tape_T (+ dtype)
    transpose_copy_probe_kernel<<<TAPE / 128, 256>>>(
        tape, out, (const int*)input_indices);

    // K2: gather + HFMA2 dot + activation + scatter via real output_indices
    gather_scatter_kernel<<<OUT / 32, 512>>>(weights, bias, input_indices,
                                             output_indices, act_ids, out);
}